// round 6
// baseline (speedup 1.0000x reference)
#include <cuda_runtime.h>
#include <math.h>

#define B_     16
#define N_     4096
#define LD_    256
#define H_     8
#define DH_    64
#define W_     128
#define INNER_ 512
#define FF_    1024
#define M_     (B_*N_)

// ---------------- scratch (device globals: no allocation) ----------------
static __device__ float g_h  [(size_t)M_*LD_];
static __device__ float g_y  [(size_t)M_*LD_];
static __device__ float g_qkv[(size_t)M_*3*INNER_];
static __device__ float g_q  [(size_t)M_*INNER_];
static __device__ float g_k  [(size_t)M_*INNER_];
static __device__ float g_v  [(size_t)M_*INNER_];
static __device__ float g_o  [(size_t)M_*INNER_];
static __device__ float g_ff [(size_t)M_*FF_];

typedef unsigned long long u64t;

// SGEMM dynamic smem layout
#define AS_STRIDE 264                         // 256 duplicated floats + 8 pad
#define AS_FLOATS (2*16*AS_STRIDE)            // 8448
#define BS_FLOATS (2*16*128)                  // 4096
#define SGEMM_SMEM ((AS_FLOATS + BS_FLOATS)*4)  // 50176 bytes

__device__ __forceinline__ float warp_sum(float v){
  #pragma unroll
  for (int o = 16; o > 0; o >>= 1) v += __shfl_xor_sync(0xffffffffu, v, o);
  return v;
}

__device__ __forceinline__ u64t dup_f32(float a){
  u64t r;
  unsigned int ai = __float_as_uint(a);
  asm("mov.b64 %0, {%1, %1};" : "=l"(r) : "r"(ai));
  return r;
}
__device__ __forceinline__ void unpack_f32x2(u64t p, float& lo, float& hi){
  unsigned int l, h;
  asm("mov.b64 {%0, %1}, %2;" : "=r"(l), "=r"(h) : "l"(p));
  lo = __uint_as_float(l); hi = __uint_as_float(h);
}
// d = a*b + d   (packed f32x2)
__device__ __forceinline__ void ffma2(u64t& d, u64t a, u64t b){
  asm("fma.rn.f32x2 %0, %1, %2, %0;" : "+l"(d) : "l"(a), "l"(b));
}
// d = d*b   (packed f32x2)
__device__ __forceinline__ void fmul2(u64t& d, u64t b){
  asm("mul.rn.f32x2 %0, %0, %1;" : "+l"(d) : "l"(b));
}

// ---------------- embed: h = x@W_exp + b_exp + pos_emb ----------------
__global__ void embed_kernel(const float* __restrict__ x, const float* __restrict__ Wexp,
                             const float* __restrict__ bexp, const float* __restrict__ pos){
  const int idx = blockIdx.x*256 + threadIdx.x;   // over M_*64 float4s
  const int m  = idx >> 6;
  const int c4 = idx & 63;
  const int n  = m & (N_-1);
  const float x0 = x[2*m], x1 = x[2*m+1];
  const float4 w0 = ((const float4*)Wexp)[c4];
  const float4 w1 = ((const float4*)Wexp)[64 + c4];
  const float4 be = ((const float4*)bexp)[c4];
  const float4 pe = ((const float4*)pos)[(size_t)n*64 + c4];
  float4 r;
  r.x = fmaf(x0, w0.x, fmaf(x1, w1.x, be.x + pe.x));
  r.y = fmaf(x0, w0.y, fmaf(x1, w1.y, be.y + pe.y));
  r.z = fmaf(x0, w0.z, fmaf(x1, w1.z, be.z + pe.z));
  r.w = fmaf(x0, w0.w, fmaf(x1, w1.w, be.w + pe.w));
  ((float4*)g_h)[idx] = r;
}

// ---------------- layernorm: warp per row (two-pass variance) ----------------
__global__ void ln_kernel(const float* __restrict__ in, const float* __restrict__ gg,
                          const float* __restrict__ bb, float* __restrict__ out){
  const int gw   = (blockIdx.x*blockDim.x + threadIdx.x) >> 5;
  const int lane = threadIdx.x & 31;
  const float* rowp = in + (size_t)gw*LD_;
  float v[8];
  {
    float4 a = *(const float4*)(rowp + lane*4);
    float4 c = *(const float4*)(rowp + 128 + lane*4);
    v[0]=a.x; v[1]=a.y; v[2]=a.z; v[3]=a.w;
    v[4]=c.x; v[5]=c.y; v[6]=c.z; v[7]=c.w;
  }
  float s = 0.f;
  #pragma unroll
  for (int i=0;i<8;i++) s += v[i];
  s = warp_sum(s);
  const float mean = s * (1.f/256.f);
  float sq = 0.f;
  #pragma unroll
  for (int i=0;i<8;i++){ float d = v[i]-mean; sq = fmaf(d,d,sq); }
  sq = warp_sum(sq);
  const float inv = rsqrtf(sq*(1.f/256.f) + 1e-5f);
  float gv[8], bv[8];
  {
    float4 a = *(const float4*)(gg + lane*4);
    float4 c = *(const float4*)(gg + 128 + lane*4);
    gv[0]=a.x; gv[1]=a.y; gv[2]=a.z; gv[3]=a.w; gv[4]=c.x; gv[5]=c.y; gv[6]=c.z; gv[7]=c.w;
    float4 e = *(const float4*)(bb + lane*4);
    float4 f = *(const float4*)(bb + 128 + lane*4);
    bv[0]=e.x; bv[1]=e.y; bv[2]=e.z; bv[3]=e.w; bv[4]=f.x; bv[5]=f.y; bv[6]=f.z; bv[7]=f.w;
  }
  float o[8];
  #pragma unroll
  for (int i=0;i<8;i++) o[i] = fmaf((v[i]-mean)*inv, gv[i], bv[i]);
  float* op = out + (size_t)gw*LD_;
  *(float4*)(op + lane*4)       = make_float4(o[0],o[1],o[2],o[3]);
  *(float4*)(op + 128 + lane*4) = make_float4(o[4],o[5],o[6],o[7]);
}

// ---------------- generic SGEMM 128x128x16, double-buffered, FFMA2 inner loop ----
// Dynamic smem (50176 B): A tile stored DUPLICATED as f32x2 pairs
// (As[k][2r] = As[k][2r+1] = A[r][k]) -> inner loop has NO register-dup MOVs:
// 4x LDS.128 (A dups, broadcast) + 2x LDS.128 (B pairs, conflict-free) + 32 FFMA2.
// Thread (tx,ty) owns rows [ty*8, ty*8+8) and cols {tx*4..+3} U {64+tx*4..+3}.
// mode 0: C = A@B        mode 1: C += A@B
// mode 2: C = gelu(A@B + bias)   mode 3: C += A@B + bias
__global__ __launch_bounds__(256, 2)
void sgemm_kernel(const float* __restrict__ A, const float* __restrict__ Bw,
                  float* __restrict__ C, const float* __restrict__ bias,
                  int N, int K, int mode)
{
  extern __shared__ __align__(16) float smem[];
  float* Asm = smem;                    // [2][16][AS_STRIDE]
  float* Bsm = smem + AS_FLOATS;        // [2][16][128]
  #define AS_(b,k,c) Asm[((b)*16 + (k))*AS_STRIDE + (c)]
  #define BS_(b,k,c) Bsm[((b)*16 + (k))*128 + (c)]

  const int tid = threadIdx.x;
  const int tx = tid & 15;
  const int ty = tid >> 4;
  const int bx = blockIdx.x;
  const int by = blockIdx.y;

  const float* Ab = A  + (size_t)by*128*K;
  const float* Bb = Bw + (size_t)bx*128;

  const int ar = tid >> 2;         // 0..63
  const int ac = (tid & 3) * 4;    // 0,4,8,12
  const int br = tid >> 5;         // 0..7
  const int bc = (tid & 31) * 4;   // 0..124

  float4 aR0, aR1, bR0, bR1;
  u64t accp[8][4];
  #pragma unroll
  for (int i=0;i<8;i++)
    #pragma unroll
    for (int jp=0;jp<4;jp++) accp[i][jp] = 0ull;   // (0.0f, 0.0f)

  // prologue: tile 0
  aR0 = *(const float4*)(Ab + (size_t)ar*K + ac);
  aR1 = *(const float4*)(Ab + (size_t)(ar+64)*K + ac);
  bR0 = *(const float4*)(Bb + (size_t)br*N + bc);
  bR1 = *(const float4*)(Bb + (size_t)(br+8)*N + bc);
  *(float2*)&AS_(0,ac+0,2*ar)      = make_float2(aR0.x, aR0.x);
  *(float2*)&AS_(0,ac+1,2*ar)      = make_float2(aR0.y, aR0.y);
  *(float2*)&AS_(0,ac+2,2*ar)      = make_float2(aR0.z, aR0.z);
  *(float2*)&AS_(0,ac+3,2*ar)      = make_float2(aR0.w, aR0.w);
  *(float2*)&AS_(0,ac+0,2*(ar+64)) = make_float2(aR1.x, aR1.x);
  *(float2*)&AS_(0,ac+1,2*(ar+64)) = make_float2(aR1.y, aR1.y);
  *(float2*)&AS_(0,ac+2,2*(ar+64)) = make_float2(aR1.z, aR1.z);
  *(float2*)&AS_(0,ac+3,2*(ar+64)) = make_float2(aR1.w, aR1.w);
  *(float4*)&BS_(0,br,bc)   = bR0;
  *(float4*)&BS_(0,br+8,bc) = bR1;
  __syncthreads();

  const int nt = K >> 4;
  for (int t=0; t<nt; t++){
    const int buf = t & 1;
    if (t+1 < nt){
      const int k0 = (t+1) << 4;
      aR0 = *(const float4*)(Ab + (size_t)ar*K + k0 + ac);
      aR1 = *(const float4*)(Ab + (size_t)(ar+64)*K + k0 + ac);
      bR0 = *(const float4*)(Bb + (size_t)(k0+br)*N + bc);
      bR1 = *(const float4*)(Bb + (size_t)(k0+br+8)*N + bc);
    }
    #pragma unroll
    for (int k=0;k<16;k++){
      const ulonglong2* Ak = (const ulonglong2*)&AS_(buf,k,ty*16);
      ulonglong2 aA = Ak[0], aB = Ak[1], aC = Ak[2], aD = Ak[3];
      u64t ad[8] = {aA.x, aA.y, aB.x, aB.y, aC.x, aC.y, aD.x, aD.y};
      ulonglong2 bA = *(const ulonglong2*)&BS_(buf,k,tx*4);       // cols tx*4..+3
      ulonglong2 bB = *(const ulonglong2*)&BS_(buf,k,64 + tx*4);  // cols 64+tx*4..+3
      u64t bp[4] = {bA.x, bA.y, bB.x, bB.y};
      #pragma unroll
      for (int i=0;i<8;i++)
        #pragma unroll
        for (int jp=0;jp<4;jp++)
          ffma2(accp[i][jp], ad[i], bp[jp]);
    }
    if (t+1 < nt){
      const int nb = buf ^ 1;
      *(float2*)&AS_(nb,ac+0,2*ar)      = make_float2(aR0.x, aR0.x);
      *(float2*)&AS_(nb,ac+1,2*ar)      = make_float2(aR0.y, aR0.y);
      *(float2*)&AS_(nb,ac+2,2*ar)      = make_float2(aR0.z, aR0.z);
      *(float2*)&AS_(nb,ac+3,2*ar)      = make_float2(aR0.w, aR0.w);
      *(float2*)&AS_(nb,ac+0,2*(ar+64)) = make_float2(aR1.x, aR1.x);
      *(float2*)&AS_(nb,ac+1,2*(ar+64)) = make_float2(aR1.y, aR1.y);
      *(float2*)&AS_(nb,ac+2,2*(ar+64)) = make_float2(aR1.z, aR1.z);
      *(float2*)&AS_(nb,ac+3,2*(ar+64)) = make_float2(aR1.w, aR1.w);
      *(float4*)&BS_(nb,br,bc)   = bR0;
      *(float4*)&BS_(nb,br+8,bc) = bR1;
      __syncthreads();
    }
  }

  const size_t crow = (size_t)by*128 + ty*8;
  const int ccol = bx*128 + tx*4;    // group 0; group 1 at +64
  float bvv[8];
  if (mode >= 2){
    float4 q0 = *(const float4*)(bias + ccol);
    float4 q1 = *(const float4*)(bias + ccol + 64);
    bvv[0]=q0.x; bvv[1]=q0.y; bvv[2]=q0.z; bvv[3]=q0.w;
    bvv[4]=q1.x; bvv[5]=q1.y; bvv[6]=q1.z; bvv[7]=q1.w;
  }
  #pragma unroll
  for (int i=0;i<8;i++){
    float* cp  = C + (crow+i)*N + ccol;
    float* cp2 = cp + 64;
    float vals[8];
    #pragma unroll
    for (int jp=0;jp<4;jp++)
      unpack_f32x2(accp[i][jp], vals[2*jp], vals[2*jp+1]);
    if (mode == 2){
      #pragma unroll
      for (int j=0;j<8;j++){
        float u = vals[j] + bvv[j];
        vals[j] = 0.5f*u*(1.f + erff(u*0.70710678118654752f));
      }
    } else if (mode == 3){
      #pragma unroll
      for (int j=0;j<8;j++) vals[j] += bvv[j];
    }
    if (mode == 1 || mode == 3){
      float4 o0 = *(const float4*)cp;
      float4 o1 = *(const float4*)cp2;
      vals[0]+=o0.x; vals[1]+=o0.y; vals[2]+=o0.z; vals[3]+=o0.w;
      vals[4]+=o1.x; vals[5]+=o1.y; vals[6]+=o1.z; vals[7]+=o1.w;
    }
    *(float4*)cp  = make_float4(vals[0],vals[1],vals[2],vals[3]);
    *(float4*)cp2 = make_float4(vals[4],vals[5],vals[6],vals[7]);
  }
  #undef AS_
  #undef BS_
}

// ---------------- rotary + head split: qkv[M,1536] -> q,k,v [B*H, N, 64] --------
__global__ void rotary_kernel(){
  const int idx = blockIdx.x*256 + threadIdx.x;   // ((m*H + h)*32 + d)
  const int d  = idx & 31;
  const int mh = idx >> 5;
  const int h  = mh & (H_-1);
  const int m  = mh >> 3;
  const int n  = m & (N_-1);
  const int b  = m >> 12;
  const float* base = g_qkv + (size_t)m*1536 + h*64;
  const float q0 = base[d],        q1 = base[32+d];
  const float k0 = base[512+d],    k1 = base[512+32+d];
  const float v0 = base[1024+d],   v1 = base[1024+32+d];
  // inv_freq = 10000^{-d/32} = 2^{-d * log2(10000)/32}
  const float invf = exp2f(-(float)d * 0.41524101186092028f);
  const float ang = (float)n * invf;
  float sn, cs;
  sincosf(ang, &sn, &cs);
  const float scale = 0.125f;   // DH^-0.5
  const size_t ob = ((size_t)(b*H_ + h)*N_ + n)*64 + d;
  g_q[ob]    = (q0*cs - q1*sn) * scale;
  g_q[ob+32] = (q1*cs + q0*sn) * scale;
  g_k[ob]    =  k0*cs - k1*sn;
  g_k[ob+32] =  k1*cs + k0*sn;
  g_v[ob]    =  v0;
  g_v[ob+32] =  v1;
}

// ---------------- local attention: 1 CTA per (window, b*h), flash softmax --------
// smem K/V rows padded to stride 68 floats: 16B-chunk index = 17*row + c
// == (row + c) mod 8  -> per-phase 8 lanes hit 8 distinct 16B banks (conflict-free).
// Chunked branchless online softmax: 16 scores -> one rescale -> 16 accumulates.
#define KVSTRIDE 68
__global__ __launch_bounds__(128, 1)
void attn_kernel(){
  extern __shared__ float sm[];
  float* ksm = sm;                    // [256][KVSTRIDE]
  float* vsm = sm + 256*KVSTRIDE;     // [256][KVSTRIDE]
  const int ww = blockIdx.x;
  const int bh = blockIdx.y;
  const int li = threadIdx.x;
  const size_t headbase = (size_t)bh * N_ * DH_;
  const int nslots = (ww==0) ? 128 : 256;
  const int slot0  = 256 - nslots;
  const int kbase  = ww*W_ - 128;   // global n of slot 0

  for (int t = li; t < nslots*16; t += 128){
    const int slot = slot0 + (t >> 4);
    const int c4   = (t & 15) * 4;
    const size_t g = headbase + (size_t)(kbase + slot)*DH_ + c4;
    *(float4*)(ksm + slot*KVSTRIDE + c4) = *(const float4*)(g_k + g);
    *(float4*)(vsm + slot*KVSTRIDE + c4) = *(const float4*)(g_v + g);
  }

  u64t qp[32];
  {
    const float* qrow = g_q + headbase + (size_t)(ww*W_ + li)*DH_;
    const ulonglong2* qv = (const ulonglong2*)qrow;
    #pragma unroll
    for (int i=0;i<16;i++){ ulonglong2 t2 = qv[i]; qp[2*i]=t2.x; qp[2*i+1]=t2.y; }
  }
  __syncthreads();

  u64t accp[32];
  #pragma unroll
  for (int d=0; d<32; d++) accp[d]=0ull;
  float mval = -3.0e38f, lsum = 0.f;

  // valid keys: slot kj in [li, li+128] (clamped to [128,..] in first window)
  const int lo = (ww==0) ? 128 : li;
  const int hi = li + 128;

  for (int base = lo; base <= hi; base += 16){
    const int cnt = min(16, hi - base + 1);
    float sc[16];
    float cmax = -3.0e38f;
    #pragma unroll
    for (int c=0;c<16;c++){
      if (c < cnt){
        const ulonglong2* kr = (const ulonglong2*)(ksm + (base+c)*KVSTRIDE);
        u64t sp[4] = {0ull,0ull,0ull,0ull};
        #pragma unroll
        for (int i=0;i<16;i++){
          ulonglong2 kk = kr[i];
          ffma2(sp[(2*i)   & 3], qp[2*i],   kk.x);
          ffma2(sp[(2*i+1) & 3], qp[2*i+1], kk.y);
        }
        float l0,h0,l1,h1,l2,h2,l3,h3;
        unpack_f32x2(sp[0], l0, h0); unpack_f32x2(sp[1], l1, h1);
        unpack_f32x2(sp[2], l2, h2); unpack_f32x2(sp[3], l3, h3);
        const float s = ((l0+h0)+(l1+h1)) + ((l2+h2)+(l3+h3));
        sc[c] = s;
        cmax = fmaxf(cmax, s);
      }
    }
    // one deterministic rescale per chunk (no per-key divergence)
    const float newm = fmaxf(mval, cmax);
    const float corr = __expf(mval - newm);   // 0 on first chunk (mval=-3e38)
    mval = newm;
    lsum *= corr;
    const u64t cd = dup_f32(corr);
    #pragma unroll
    for (int i=0;i<32;i++) fmul2(accp[i], cd);
    #pragma unroll
    for (int c=0;c<16;c++){
      if (c < cnt){
        const float p = __expf(sc[c] - mval);
        lsum += p;
        const u64t pd = dup_f32(p);
        const ulonglong2* vr = (const ulonglong2*)(vsm + (base+c)*KVSTRIDE);
        #pragma unroll
        for (int i=0;i<16;i++){
          ulonglong2 vv = vr[i];
          ffma2(accp[2*i],   pd, vv.x);
          ffma2(accp[2*i+1], pd, vv.y);
        }
      }
    }
  }
  const float invl = 1.f / lsum;
  __syncthreads();

  // stage through smem (stride 68) for coalesced gmem stores
  float* osm = sm;
  #pragma unroll
  for (int dp=0; dp<32; dp++){
    float lo2, hi2;
    unpack_f32x2(accp[dp], lo2, hi2);
    *(float2*)(osm + li*KVSTRIDE + dp*2) = make_float2(lo2*invl, hi2*invl);
  }
  __syncthreads();
  const int b = bh >> 3, h = bh & 7;
  const size_t obase = ((size_t)(b*N_ + ww*W_))*INNER_ + h*DH_;
  for (int t = li; t < 128*16; t += 128){
    const int r  = t >> 4;
    const int c4 = (t & 15)*4;
    *(float4*)(g_o + obase + (size_t)r*INNER_ + c4) = *(float4*)(osm + r*KVSTRIDE + c4);
  }
}

// ---------------- final LN + logits matvec + slack slice ----------------
__global__ void final_kernel(const float* __restrict__ gg, const float* __restrict__ bb,
                             const float* __restrict__ wl, float* __restrict__ out){
  const int gw   = (blockIdx.x*blockDim.x + threadIdx.x) >> 5;
  const int lane = threadIdx.x & 31;
  const float* rowp = g_h + (size_t)gw*LD_;
  float v[8];
  {
    float4 a = *(const float4*)(rowp + lane*4);
    float4 c = *(const float4*)(rowp + 128 + lane*4);
    v[0]=a.x; v[1]=a.y; v[2]=a.z; v[3]=a.w; v[4]=c.x; v[5]=c.y; v[6]=c.z; v[7]=c.w;
  }
  float s = 0.f;
  #pragma unroll
  for (int i=0;i<8;i++) s += v[i];
  s = warp_sum(s);
  const float mean = s * (1.f/256.f);
  float sq = 0.f;
  #pragma unroll
  for (int i=0;i<8;i++){ float d = v[i]-mean; sq = fmaf(d,d,sq); }
  sq = warp_sum(sq);
  const float inv = rsqrtf(sq*(1.f/256.f) + 1e-5f);
  float gv[8], bvl[8], wv[8];
  {
    float4 a = *(const float4*)(gg + lane*4);
    float4 c = *(const float4*)(gg + 128 + lane*4);
    gv[0]=a.x; gv[1]=a.y; gv[2]=a.z; gv[3]=a.w; gv[4]=c.x; gv[5]=c.y; gv[6]=c.z; gv[7]=c.w;
    float4 e = *(const float4*)(bb + lane*4);
    float4 f = *(const float4*)(bb + 128 + lane*4);
    bvl[0]=e.x; bvl[1]=e.y; bvl[2]=e.z; bvl[3]=e.w; bvl[4]=f.x; bvl[5]=f.y; bvl[6]=f.z; bvl[7]=f.w;
    float4 p = *(const float4*)(wl + lane*4);
    float4 r = *(const float4*)(wl + 128 + lane*4);
    wv[0]=p.x; wv[1]=p.y; wv[2]=p.z; wv[3]=p.w; wv[4]=r.x; wv[5]=r.y; wv[6]=r.z; wv[7]=r.w;
  }
  float dot = 0.f;
  #pragma unroll
  for (int i=0;i<8;i++) dot = fmaf(fmaf((v[i]-mean)*inv, gv[i], bvl[i]), wv[i], dot);
  dot = warp_sum(dot);
  if (lane == 0){
    const int n = gw & (N_-1);
    const int b = gw >> 12;
    if (n >= 50 && n < N_-50)
      out[(size_t)b*(N_-100) + (n-50)] = dot;
  }
}

// ---------------- launch ----------------
extern "C" void kernel_launch(void* const* d_in, const int* in_sizes, int n_in,
                              void* d_out, int out_size){
  const float* x     = (const float*)d_in[0];
  const float* W_exp = (const float*)d_in[1];
  const float* b_exp = (const float*)d_in[2];
  const float* pos   = (const float*)d_in[3];
  const float* lag   = (const float*)d_in[4];
  const float* lab   = (const float*)d_in[5];
  const float* Wqkv  = (const float*)d_in[6];
  const float* Wout  = (const float*)d_in[7];
  const float* lfg   = (const float*)d_in[8];
  const float* lfb   = (const float*)d_in[9];
  const float* W1    = (const float*)d_in[10];
  const float* b1    = (const float*)d_in[11];
  const float* W2    = (const float*)d_in[12];
  const float* b2    = (const float*)d_in[13];
  const float* lnfg  = (const float*)d_in[14];
  const float* lnfb  = (const float*)d_in[15];
  const float* Wl    = (const float*)d_in[16];
  float* out = (float*)d_out;

  const int attn_smem = 2*256*KVSTRIDE*4;
  cudaFuncSetAttribute(attn_kernel,  cudaFuncAttributeMaxDynamicSharedMemorySize, attn_smem);
  cudaFuncSetAttribute(sgemm_kernel, cudaFuncAttributeMaxDynamicSharedMemorySize, SGEMM_SMEM);

  float *p_h, *p_y, *p_qkv, *p_o, *p_ff;
  cudaGetSymbolAddress((void**)&p_h,   g_h);
  cudaGetSymbolAddress((void**)&p_y,   g_y);
  cudaGetSymbolAddress((void**)&p_qkv, g_qkv);
  cudaGetSymbolAddress((void**)&p_o,   g_o);
  cudaGetSymbolAddress((void**)&p_ff,  g_ff);

  embed_kernel<<<M_*64/256, 256>>>(x, W_exp, b_exp, pos);

  for (int l = 0; l < 4; l++){
    ln_kernel<<<M_/8, 256>>>(p_h, lag + l*LD_, lab + l*LD_, p_y);
    sgemm_kernel<<<dim3(12, M_/128), 256, SGEMM_SMEM>>>(p_y, Wqkv + (size_t)l*LD_*3*INNER_, p_qkv, nullptr, 3*INNER_, LD_, 0);
    rotary_kernel<<<M_*H_*32/256, 256>>>();
    attn_kernel<<<dim3(N_/W_, B_*H_), 128, attn_smem>>>();
    sgemm_kernel<<<dim3(2, M_/128), 256, SGEMM_SMEM>>>(p_o, Wout + (size_t)l*INNER_*LD_, p_h, nullptr, LD_, INNER_, 1);
    ln_kernel<<<M_/8, 256>>>(p_h, lfg + l*LD_, lfb + l*LD_, p_y);
    sgemm_kernel<<<dim3(8, M_/128), 256, SGEMM_SMEM>>>(p_y, W1 + (size_t)l*LD_*FF_, p_ff, b1 + l*FF_, FF_, LD_, 2);
    sgemm_kernel<<<dim3(2, M_/128), 256, SGEMM_SMEM>>>(p_ff, W2 + (size_t)l*FF_*LD_, p_h, b2 + l*LD_, LD_, FF_, 3);
  }

  final_kernel<<<M_/8, 256>>>(lnfg, lnfb, Wl, out);
}

// round 11
// speedup vs baseline: 1.8220x; 1.8220x over previous
#include <cuda_runtime.h>
#include <math.h>

#define B_     16
#define N_     4096
#define LD_    256
#define H_     8
#define DH_    64
#define W_     128
#define INNER_ 512
#define FF_    1024
#define M_     (B_*N_)

// ---------------- scratch (device globals: no allocation) ----------------
static __device__ float g_h  [(size_t)M_*LD_];
static __device__ float g_y  [(size_t)M_*LD_];
static __device__ float g_qkv[(size_t)M_*3*INNER_];
static __device__ float g_q  [(size_t)M_*INNER_];
static __device__ float g_k  [(size_t)M_*INNER_];
static __device__ float g_v  [(size_t)M_*INNER_];
static __device__ float g_o  [(size_t)M_*INNER_];
static __device__ float g_ff [(size_t)M_*FF_];

typedef unsigned long long u64t;

// tf32 GEMM smem: A [2][128][36], B [2][32][136]  (float words)
#define TA_BUF 4608            // 128*36
#define TB_BUF 4352            // 32*136
#define TGEMM_SMEM ((2*TA_BUF + 2*TB_BUF)*4)   // 71680 bytes

__device__ __forceinline__ float warp_sum(float v){
  #pragma unroll
  for (int o = 16; o > 0; o >>= 1) v += __shfl_xor_sync(0xffffffffu, v, o);
  return v;
}

__device__ __forceinline__ u64t dup_f32(float a){
  u64t r;
  unsigned int ai = __float_as_uint(a);
  asm("mov.b64 %0, {%1, %1};" : "=l"(r) : "r"(ai));
  return r;
}
__device__ __forceinline__ void unpack_f32x2(u64t p, float& lo, float& hi){
  unsigned int l, h;
  asm("mov.b64 {%0, %1}, %2;" : "=r"(l), "=r"(h) : "l"(p));
  lo = __uint_as_float(l); hi = __uint_as_float(h);
}
__device__ __forceinline__ void ffma2(u64t& d, u64t a, u64t b){
  asm("fma.rn.f32x2 %0, %1, %2, %0;" : "+l"(d) : "l"(a), "l"(b));
}
__device__ __forceinline__ void fmul2(u64t& d, u64t b){
  asm("mul.rn.f32x2 %0, %0, %1;" : "+l"(d) : "l"(b));
}
__device__ __forceinline__ unsigned int f2tf32(float f){
  unsigned int r;
  asm("cvt.rna.tf32.f32 %0, %1;" : "=r"(r) : "f"(f));
  return r;
}
// D += A(16x8,row) * B(8x8,col)  tf32
__device__ __forceinline__ void mma_tf32(float* c, const unsigned int* a, const unsigned int* b){
  asm("mma.sync.aligned.m16n8k8.row.col.f32.tf32.tf32.f32 "
      "{%0,%1,%2,%3}, {%4,%5,%6,%7}, {%8,%9}, {%0,%1,%2,%3};"
      : "+f"(c[0]), "+f"(c[1]), "+f"(c[2]), "+f"(c[3])
      : "r"(a[0]), "r"(a[1]), "r"(a[2]), "r"(a[3]), "r"(b[0]), "r"(b[1]));
}

// ---------------- embed: h = x@W_exp + b_exp + pos_emb ----------------
__global__ void embed_kernel(const float* __restrict__ x, const float* __restrict__ Wexp,
                             const float* __restrict__ bexp, const float* __restrict__ pos){
  const int idx = blockIdx.x*256 + threadIdx.x;
  const int m  = idx >> 6;
  const int c4 = idx & 63;
  const int n  = m & (N_-1);
  const float x0 = x[2*m], x1 = x[2*m+1];
  const float4 w0 = ((const float4*)Wexp)[c4];
  const float4 w1 = ((const float4*)Wexp)[64 + c4];
  const float4 be = ((const float4*)bexp)[c4];
  const float4 pe = ((const float4*)pos)[(size_t)n*64 + c4];
  float4 r;
  r.x = fmaf(x0, w0.x, fmaf(x1, w1.x, be.x + pe.x));
  r.y = fmaf(x0, w0.y, fmaf(x1, w1.y, be.y + pe.y));
  r.z = fmaf(x0, w0.z, fmaf(x1, w1.z, be.z + pe.z));
  r.w = fmaf(x0, w0.w, fmaf(x1, w1.w, be.w + pe.w));
  ((float4*)g_h)[idx] = r;
}

// ---------------- layernorm ----------------
__global__ void ln_kernel(const float* __restrict__ in, const float* __restrict__ gg,
                          const float* __restrict__ bb, float* __restrict__ out){
  const int gw   = (blockIdx.x*blockDim.x + threadIdx.x) >> 5;
  const int lane = threadIdx.x & 31;
  const float* rowp = in + (size_t)gw*LD_;
  float v[8];
  {
    float4 a = *(const float4*)(rowp + lane*4);
    float4 c = *(const float4*)(rowp + 128 + lane*4);
    v[0]=a.x; v[1]=a.y; v[2]=a.z; v[3]=a.w;
    v[4]=c.x; v[5]=c.y; v[6]=c.z; v[7]=c.w;
  }
  float s = 0.f;
  #pragma unroll
  for (int i=0;i<8;i++) s += v[i];
  s = warp_sum(s);
  const float mean = s * (1.f/256.f);
  float sq = 0.f;
  #pragma unroll
  for (int i=0;i<8;i++){ float d = v[i]-mean; sq = fmaf(d,d,sq); }
  sq = warp_sum(sq);
  const float inv = rsqrtf(sq*(1.f/256.f) + 1e-5f);
  float gv[8], bv[8];
  {
    float4 a = *(const float4*)(gg + lane*4);
    float4 c = *(const float4*)(gg + 128 + lane*4);
    gv[0]=a.x; gv[1]=a.y; gv[2]=a.z; gv[3]=a.w; gv[4]=c.x; gv[5]=c.y; gv[6]=c.z; gv[7]=c.w;
    float4 e = *(const float4*)(bb + lane*4);
    float4 f = *(const float4*)(bb + 128 + lane*4);
    bv[0]=e.x; bv[1]=e.y; bv[2]=e.z; bv[3]=e.w; bv[4]=f.x; bv[5]=f.y; bv[6]=f.z; bv[7]=f.w;
  }
  float o[8];
  #pragma unroll
  for (int i=0;i<8;i++) o[i] = fmaf((v[i]-mean)*inv, gv[i], bv[i]);
  float* op = out + (size_t)gw*LD_;
  *(float4*)(op + lane*4)       = make_float4(o[0],o[1],o[2],o[3]);
  *(float4*)(op + 128 + lane*4) = make_float4(o[4],o[5],o[6],o[7]);
}

// ---------------- tf32 tensor-core GEMM 128x128, K-tile 32, double-buffered -----
// 8 warps (2x4); warp tile 64x32; mma.sync.m16n8k8.tf32, fp32 accumulate.
// smem strides: A 36 (frag LDS bank-bijective), B 136 (bank-bijective).
// mode 0: C = A@B   mode 1: C += A@B   mode 2: C = gelu(A@B+bias)  mode 3: C += A@B+bias
__global__ __launch_bounds__(256)
void tgemm_kernel(const float* __restrict__ A, const float* __restrict__ Bw,
                  float* __restrict__ C, const float* __restrict__ bias,
                  int N, int K, int mode)
{
  extern __shared__ __align__(16) float smem[];
  float* Asm = smem;                 // [2][128][36]
  float* Bsm = smem + 2*TA_BUF;      // [2][32][136]

  const int tid = threadIdx.x;
  const int bx = blockIdx.x;
  const int by = blockIdx.y;
  const int wid = tid >> 5, lane = tid & 31;
  const int wy = wid >> 2, wx = wid & 3;     // warp grid 2x4
  const int g = lane >> 2, tt = lane & 3;

  const float* Ag = A  + (size_t)by*128*K;
  const float* Bg = Bw + (size_t)bx*128;

  // staging indices
  const int arow = tid >> 3;
  const int ac4  = tid & 7;
  const int brow = tid >> 5;
  const int bc4  = tid & 31;

  float acc[4][4][4];
  #pragma unroll
  for (int mf=0; mf<4; mf++)
    #pragma unroll
    for (int nf=0; nf<4; nf++)
      #pragma unroll
      for (int r=0; r<4; r++) acc[mf][nf][r] = 0.f;

  float4 pa[4], pb[4];

  // prologue: stage tile 0
  #pragma unroll
  for (int p=0; p<4; p++){
    const int row = arow + p*32;
    pa[p] = *(const float4*)(Ag + (size_t)row*K + ac4*4);
    pb[p] = *(const float4*)(Bg + (size_t)(brow + p*8)*N + bc4*4);
  }
  #pragma unroll
  for (int p=0; p<4; p++){
    const int row = arow + p*32;
    uint4 ta = make_uint4(f2tf32(pa[p].x), f2tf32(pa[p].y), f2tf32(pa[p].z), f2tf32(pa[p].w));
    *(uint4*)&Asm[row*36 + ac4*4] = ta;
    uint4 tb = make_uint4(f2tf32(pb[p].x), f2tf32(pb[p].y), f2tf32(pb[p].z), f2tf32(pb[p].w));
    *(uint4*)&Bsm[(brow + p*8)*136 + bc4*4] = tb;
  }
  __syncthreads();

  const int nt = K >> 5;   // K-tiles of 32
  for (int t=0; t<nt; t++){
    const int buf = t & 1;
    if (t+1 < nt){
      const int k0 = (t+1) << 5;
      #pragma unroll
      for (int p=0; p<4; p++){
        const int row = arow + p*32;
        pa[p] = *(const float4*)(Ag + (size_t)row*K + k0 + ac4*4);
        pb[p] = *(const float4*)(Bg + (size_t)(k0 + brow + p*8)*N + bc4*4);
      }
    }
    const float* Ab = Asm + buf*TA_BUF;
    const float* Bb = Bsm + buf*TB_BUF;
    #pragma unroll
    for (int ks=0; ks<4; ks++){
      unsigned int af[4][4], bf[4][2];
      #pragma unroll
      for (int mf=0; mf<4; mf++){
        const int rb = wy*64 + mf*16;
        af[mf][0] = __float_as_uint(Ab[(rb + g    )*36 + ks*8 + tt    ]);
        af[mf][1] = __float_as_uint(Ab[(rb + g + 8)*36 + ks*8 + tt    ]);
        af[mf][2] = __float_as_uint(Ab[(rb + g    )*36 + ks*8 + tt + 4]);
        af[mf][3] = __float_as_uint(Ab[(rb + g + 8)*36 + ks*8 + tt + 4]);
      }
      #pragma unroll
      for (int nf=0; nf<4; nf++){
        const int cb = wx*32 + nf*8;
        bf[nf][0] = __float_as_uint(Bb[(ks*8 + tt    )*136 + cb + g]);
        bf[nf][1] = __float_as_uint(Bb[(ks*8 + tt + 4)*136 + cb + g]);
      }
      #pragma unroll
      for (int mf=0; mf<4; mf++)
        #pragma unroll
        for (int nf=0; nf<4; nf++)
          mma_tf32(acc[mf][nf], af[mf], bf[nf]);
    }
    if (t+1 < nt){
      const int nb = buf ^ 1;
      #pragma unroll
      for (int p=0; p<4; p++){
        const int row = arow + p*32;
        uint4 ta = make_uint4(f2tf32(pa[p].x), f2tf32(pa[p].y), f2tf32(pa[p].z), f2tf32(pa[p].w));
        *(uint4*)&Asm[nb*TA_BUF + row*36 + ac4*4] = ta;
        uint4 tb = make_uint4(f2tf32(pb[p].x), f2tf32(pb[p].y), f2tf32(pb[p].z), f2tf32(pb[p].w));
        *(uint4*)&Bsm[nb*TB_BUF + (brow + p*8)*136 + bc4*4] = tb;
      }
      __syncthreads();
    }
  }

  // epilogue
  #pragma unroll
  for (int mf=0; mf<4; mf++){
    const size_t r0 = (size_t)by*128 + wy*64 + mf*16 + g;
    const size_t r1 = r0 + 8;
    #pragma unroll
    for (int nf=0; nf<4; nf++){
      const int cc = bx*128 + wx*32 + nf*8 + tt*2;
      float v0 = acc[mf][nf][0], v1 = acc[mf][nf][1];
      float v2 = acc[mf][nf][2], v3 = acc[mf][nf][3];
      if (mode >= 2){
        const float2 bv = *(const float2*)(bias + cc);
        if (mode == 2){
          float u;
          u = v0 + bv.x; v0 = 0.5f*u*(1.f + erff(u*0.70710678118654752f));
          u = v1 + bv.y; v1 = 0.5f*u*(1.f + erff(u*0.70710678118654752f));
          u = v2 + bv.x; v2 = 0.5f*u*(1.f + erff(u*0.70710678118654752f));
          u = v3 + bv.y; v3 = 0.5f*u*(1.f + erff(u*0.70710678118654752f));
        } else {
          v0 += bv.x; v1 += bv.y; v2 += bv.x; v3 += bv.y;
        }
      }
      float* p0 = C + r0*N + cc;
      float* p1 = C + r1*N + cc;
      if (mode == 1 || mode == 3){
        const float2 o0 = *(const float2*)p0;
        const float2 o1 = *(const float2*)p1;
        v0 += o0.x; v1 += o0.y; v2 += o1.x; v3 += o1.y;
      }
      *(float2*)p0 = make_float2(v0, v1);
      *(float2*)p1 = make_float2(v2, v3);
    }
  }
}

// ---------------- rotary + head split ----------------
__global__ void rotary_kernel(){
  const int idx = blockIdx.x*256 + threadIdx.x;
  const int d  = idx & 31;
  const int mh = idx >> 5;
  const int h  = mh & (H_-1);
  const int m  = mh >> 3;
  const int n  = m & (N_-1);
  const int b  = m >> 12;
  const float* base = g_qkv + (size_t)m*1536 + h*64;
  const float q0 = base[d],        q1 = base[32+d];
  const float k0 = base[512+d],    k1 = base[512+32+d];
  const float v0 = base[1024+d],   v1 = base[1024+32+d];
  const float invf = exp2f(-(float)d * 0.41524101186092028f);
  const float ang = (float)n * invf;
  float sn, cs;
  sincosf(ang, &sn, &cs);
  const float scale = 0.125f;
  const size_t ob = ((size_t)(b*H_ + h)*N_ + n)*64 + d;
  g_q[ob]    = (q0*cs - q1*sn) * scale;
  g_q[ob+32] = (q1*cs + q0*sn) * scale;
  g_k[ob]    =  k0*cs - k1*sn;
  g_k[ob+32] =  k1*cs + k0*sn;
  g_v[ob]    =  v0;
  g_v[ob+32] =  v1;
}

// ---------------- local attention ----------------
#define KVSTRIDE 68
__global__ __launch_bounds__(128, 1)
void attn_kernel(){
  extern __shared__ float sm[];
  float* ksm = sm;
  float* vsm = sm + 256*KVSTRIDE;
  const int ww = blockIdx.x;
  const int bh = blockIdx.y;
  const int li = threadIdx.x;
  const size_t headbase = (size_t)bh * N_ * DH_;
  const int nslots = (ww==0) ? 128 : 256;
  const int slot0  = 256 - nslots;
  const int kbase  = ww*W_ - 128;

  for (int t = li; t < nslots*16; t += 128){
    const int slot = slot0 + (t >> 4);
    const int c4   = (t & 15) * 4;
    const size_t gg = headbase + (size_t)(kbase + slot)*DH_ + c4;
    *(float4*)(ksm + slot*KVSTRIDE + c4) = *(const float4*)(g_k + gg);
    *(float4*)(vsm + slot*KVSTRIDE + c4) = *(const float4*)(g_v + gg);
  }

  u64t qp[32];
  {
    const float* qrow = g_q + headbase + (size_t)(ww*W_ + li)*DH_;
    const ulonglong2* qv = (const ulonglong2*)qrow;
    #pragma unroll
    for (int i=0;i<16;i++){ ulonglong2 t2 = qv[i]; qp[2*i]=t2.x; qp[2*i+1]=t2.y; }
  }
  __syncthreads();

  u64t accp[32];
  #pragma unroll
  for (int d=0; d<32; d++) accp[d]=0ull;
  float mval = -3.0e38f, lsum = 0.f;

  const int lo = (ww==0) ? 128 : li;
  const int hi = li + 128;

  for (int base = lo; base <= hi; base += 16){
    const int cnt = min(16, hi - base + 1);
    float sc[16];
    float cmax = -3.0e38f;
    #pragma unroll
    for (int c=0;c<16;c++){
      if (c < cnt){
        const ulonglong2* kr = (const ulonglong2*)(ksm + (base+c)*KVSTRIDE);
        u64t sp[4] = {0ull,0ull,0ull,0ull};
        #pragma unroll
        for (int i=0;i<16;i++){
          ulonglong2 kk = kr[i];
          ffma2(sp[(2*i)   & 3], qp[2*i],   kk.x);
          ffma2(sp[(2*i+1) & 3], qp[2*i+1], kk.y);
        }
        float l0,h0,l1,h1,l2,h2,l3,h3;
        unpack_f32x2(sp[0], l0, h0); unpack_f32x2(sp[1], l1, h1);
        unpack_f32x2(sp[2], l2, h2); unpack_f32x2(sp[3], l3, h3);
        const float s = ((l0+h0)+(l1+h1)) + ((l2+h2)+(l3+h3));
        sc[c] = s;
        cmax = fmaxf(cmax, s);
      }
    }
    const float newm = fmaxf(mval, cmax);
    const float corr = __expf(mval - newm);
    mval = newm;
    lsum *= corr;
    const u64t cd = dup_f32(corr);
    #pragma unroll
    for (int i=0;i<32;i++) fmul2(accp[i], cd);
    #pragma unroll
    for (int c=0;c<16;c++){
      if (c < cnt){
        const float p = __expf(sc[c] - mval);
        lsum += p;
        const u64t pd = dup_f32(p);
        const ulonglong2* vr = (const ulonglong2*)(vsm + (base+c)*KVSTRIDE);
        #pragma unroll
        for (int i=0;i<16;i++){
          ulonglong2 vv = vr[i];
          ffma2(accp[2*i],   pd, vv.x);
          ffma2(accp[2*i+1], pd, vv.y);
        }
      }
    }
  }
  const float invl = 1.f / lsum;
  __syncthreads();

  float* osm = sm;
  #pragma unroll
  for (int dp=0; dp<32; dp++){
    float lo2, hi2;
    unpack_f32x2(accp[dp], lo2, hi2);
    *(float2*)(osm + li*KVSTRIDE + dp*2) = make_float2(lo2*invl, hi2*invl);
  }
  __syncthreads();
  const int b = bh >> 3, h = bh & 7;
  const size_t obase = ((size_t)(b*N_ + ww*W_))*INNER_ + h*DH_;
  for (int t = li; t < 128*16; t += 128){
    const int r  = t >> 4;
    const int c4 = (t & 15)*4;
    *(float4*)(g_o + obase + (size_t)r*INNER_ + c4) = *(float4*)(osm + r*KVSTRIDE + c4);
  }
}

// ---------------- final LN + logits ----------------
__global__ void final_kernel(const float* __restrict__ gg, const float* __restrict__ bb,
                             const float* __restrict__ wl, float* __restrict__ out){
  const int gw   = (blockIdx.x*blockDim.x + threadIdx.x) >> 5;
  const int lane = threadIdx.x & 31;
  const float* rowp = g_h + (size_t)gw*LD_;
  float v[8];
  {
    float4 a = *(const float4*)(rowp + lane*4);
    float4 c = *(const float4*)(rowp + 128 + lane*4);
    v[0]=a.x; v[1]=a.y; v[2]=a.z; v[3]=a.w; v[4]=c.x; v[5]=c.y; v[6]=c.z; v[7]=c.w;
  }
  float s = 0.f;
  #pragma unroll
  for (int i=0;i<8;i++) s += v[i];
  s = warp_sum(s);
  const float mean = s * (1.f/256.f);
  float sq = 0.f;
  #pragma unroll
  for (int i=0;i<8;i++){ float d = v[i]-mean; sq = fmaf(d,d,sq); }
  sq = warp_sum(sq);
  const float inv = rsqrtf(sq*(1.f/256.f) + 1e-5f);
  float gv[8], bvl[8], wv[8];
  {
    float4 a = *(const float4*)(gg + lane*4);
    float4 c = *(const float4*)(gg + 128 + lane*4);
    gv[0]=a.x; gv[1]=a.y; gv[2]=a.z; gv[3]=a.w; gv[4]=c.x; gv[5]=c.y; gv[6]=c.z; gv[7]=c.w;
    float4 e = *(const float4*)(bb + lane*4);
    float4 f = *(const float4*)(bb + 128 + lane*4);
    bvl[0]=e.x; bvl[1]=e.y; bvl[2]=e.z; bvl[3]=e.w; bvl[4]=f.x; bvl[5]=f.y; bvl[6]=f.z; bvl[7]=f.w;
    float4 p = *(const float4*)(wl + lane*4);
    float4 r = *(const float4*)(wl + 128 + lane*4);
    wv[0]=p.x; wv[1]=p.y; wv[2]=p.z; wv[3]=p.w; wv[4]=r.x; wv[5]=r.y; wv[6]=r.z; wv[7]=r.w;
  }
  float dot = 0.f;
  #pragma unroll
  for (int i=0;i<8;i++) dot = fmaf(fmaf((v[i]-mean)*inv, gv[i], bvl[i]), wv[i], dot);
  dot = warp_sum(dot);
  if (lane == 0){
    const int n = gw & (N_-1);
    const int b = gw >> 12;
    if (n >= 50 && n < N_-50)
      out[(size_t)b*(N_-100) + (n-50)] = dot;
  }
}

// ---------------- launch ----------------
extern "C" void kernel_launch(void* const* d_in, const int* in_sizes, int n_in,
                              void* d_out, int out_size){
  const float* x     = (const float*)d_in[0];
  const float* W_exp = (const float*)d_in[1];
  const float* b_exp = (const float*)d_in[2];
  const float* pos   = (const float*)d_in[3];
  const float* lag   = (const float*)d_in[4];
  const float* lab   = (const float*)d_in[5];
  const float* Wqkv  = (const float*)d_in[6];
  const float* Wout  = (const float*)d_in[7];
  const float* lfg   = (const float*)d_in[8];
  const float* lfb   = (const float*)d_in[9];
  const float* W1    = (const float*)d_in[10];
  const float* b1    = (const float*)d_in[11];
  const float* W2    = (const float*)d_in[12];
  const float* b2    = (const float*)d_in[13];
  const float* lnfg  = (const float*)d_in[14];
  const float* lnfb  = (const float*)d_in[15];
  const float* Wl    = (const float*)d_in[16];
  float* out = (float*)d_out;

  const int attn_smem = 2*256*KVSTRIDE*4;
  cudaFuncSetAttribute(attn_kernel,  cudaFuncAttributeMaxDynamicSharedMemorySize, attn_smem);
  cudaFuncSetAttribute(tgemm_kernel, cudaFuncAttributeMaxDynamicSharedMemorySize, TGEMM_SMEM);

  float *p_h, *p_y, *p_qkv, *p_o, *p_ff;
  cudaGetSymbolAddress((void**)&p_h,   g_h);
  cudaGetSymbolAddress((void**)&p_y,   g_y);
  cudaGetSymbolAddress((void**)&p_qkv, g_qkv);
  cudaGetSymbolAddress((void**)&p_o,   g_o);
  cudaGetSymbolAddress((void**)&p_ff,  g_ff);

  embed_kernel<<<M_*64/256, 256>>>(x, W_exp, b_exp, pos);

  for (int l = 0; l < 4; l++){
    ln_kernel<<<M_/8, 256>>>(p_h, lag + l*LD_, lab + l*LD_, p_y);
    tgemm_kernel<<<dim3(12, M_/128), 256, TGEMM_SMEM>>>(p_y, Wqkv + (size_t)l*LD_*3*INNER_, p_qkv, nullptr, 3*INNER_, LD_, 0);
    rotary_kernel<<<M_*H_*32/256, 256>>>();
    attn_kernel<<<dim3(N_/W_, B_*H_), 128, attn_smem>>>();
    tgemm_kernel<<<dim3(2, M_/128), 256, TGEMM_SMEM>>>(p_o, Wout + (size_t)l*INNER_*LD_, p_h, nullptr, LD_, INNER_, 1);
    ln_kernel<<<M_/8, 256>>>(p_h, lfg + l*LD_, lfb + l*LD_, p_y);
    tgemm_kernel<<<dim3(8, M_/128), 256, TGEMM_SMEM>>>(p_y, W1 + (size_t)l*LD_*FF_, p_ff, b1 + l*FF_, FF_, LD_, 2);
    tgemm_kernel<<<dim3(2, M_/128), 256, TGEMM_SMEM>>>(p_ff, W2 + (size_t)l*FF_*LD_, p_h, b2 + l*LD_, LD_, FF_, 3);
  }

  final_kernel<<<M_/8, 256>>>(lnfg, lnfb, Wl, out);
}